// round 3
// baseline (speedup 1.0000x reference)
#include <cuda_runtime.h>
#include <cuda_bf16.h>
#include <math.h>

// ---------------- problem constants ----------------
constexpr int T    = 4096;
constexpr int HID  = 2048;
constexpr int H    = 16;
constexpr int DN   = 128;   // D_NOPE
constexpr int DR   = 64;    // D_ROPE
constexpr int DQK  = 192;   // DN + DR
constexpr int DV   = 128;
constexpr int LKV  = 512;
constexpr int HKVA = LKV + DR;  // 576

// ---------------- device scratch (static, no allocs) ----------------
__device__ float g_q[(size_t)T * H * DQK];      // [T][H][192], q_pe roped in place
__device__ float g_latent[(size_t)T * HKVA];    // [T][576]
__device__ float g_kva[(size_t)T * LKV];        // rmsnormed latent[:, :512]
__device__ float g_kpe[(size_t)T * DR];         // roped k_pe
__device__ float g_kv[(size_t)T * H * (DN+DV)]; // [T][H][256]  (k_nope | v)
__device__ float g_attn[(size_t)T * H * DV];    // [T][2048]

// ---------------- generic SGEMM: C[M,N] = A[M,K] @ B[K,N] (row major) ---------
// BM=BN=128, BK=8, 256 threads, 8x8 per thread. M%128==0, K%8==0 guaranteed by
// our shapes; N edges (N=576) handled with guards.
__global__ void __launch_bounds__(256) sgemm_kernel(
    const float* __restrict__ A, const float* __restrict__ B,
    float* __restrict__ C, int M, int N, int K)
{
    constexpr int BM = 128, BN = 128, BK = 8;
    __shared__ float As[BK][BM];
    __shared__ float Bs[BK][BN];

    const int bx = blockIdx.x;          // N tiles
    const int by = blockIdx.y;          // M tiles
    const int tid = threadIdx.x;
    const int tx = tid & 15;            // 16 cols of 8
    const int ty = tid >> 4;            // 16 rows of 8

    const int a_row = tid >> 1;              // 0..127
    const int a_col = (tid & 1) * 4;         // 0 or 4
    const int b_row = tid >> 5;              // 0..7
    const int b_col = (tid & 31) * 4;        // 0..124

    const float* Ab = A + (size_t)(by * BM) * K;
    const int n_base = bx * BN;

    float acc[8][8];
#pragma unroll
    for (int i = 0; i < 8; i++)
#pragma unroll
        for (int j = 0; j < 8; j++) acc[i][j] = 0.f;

    const bool b_vec_ok = (n_base + b_col + 3) < N;

    for (int k0 = 0; k0 < K; k0 += BK) {
        // A tile (always in-bounds)
        float4 av = *(const float4*)(Ab + (size_t)a_row * K + k0 + a_col);
        As[a_col + 0][a_row] = av.x;
        As[a_col + 1][a_row] = av.y;
        As[a_col + 2][a_row] = av.z;
        As[a_col + 3][a_row] = av.w;
        // B tile (N guard on edge tile)
        float4 bv;
        if (b_vec_ok) {
            bv = *(const float4*)(B + (size_t)(k0 + b_row) * N + n_base + b_col);
        } else {
            const float* Brow = B + (size_t)(k0 + b_row) * N;
            bv.x = (n_base + b_col + 0 < N) ? Brow[n_base + b_col + 0] : 0.f;
            bv.y = (n_base + b_col + 1 < N) ? Brow[n_base + b_col + 1] : 0.f;
            bv.z = (n_base + b_col + 2 < N) ? Brow[n_base + b_col + 2] : 0.f;
            bv.w = (n_base + b_col + 3 < N) ? Brow[n_base + b_col + 3] : 0.f;
        }
        *(float4*)&Bs[b_row][b_col] = bv;
        __syncthreads();

#pragma unroll
        for (int k = 0; k < BK; k++) {
            float4 a0 = *(const float4*)&As[k][ty * 8];
            float4 a1 = *(const float4*)&As[k][ty * 8 + 4];
            float4 b0 = *(const float4*)&Bs[k][tx * 8];
            float4 b1 = *(const float4*)&Bs[k][tx * 8 + 4];
            float ra[8] = {a0.x, a0.y, a0.z, a0.w, a1.x, a1.y, a1.z, a1.w};
            float rb[8] = {b0.x, b0.y, b0.z, b0.w, b1.x, b1.y, b1.z, b1.w};
#pragma unroll
            for (int i = 0; i < 8; i++)
#pragma unroll
                for (int j = 0; j < 8; j++)
                    acc[i][j] = fmaf(ra[i], rb[j], acc[i][j]);
        }
        __syncthreads();
    }

#pragma unroll
    for (int i = 0; i < 8; i++) {
        const size_t gr = (size_t)(by * BM + ty * 8 + i);
#pragma unroll
        for (int j = 0; j < 8; j++) {
            const int gc = n_base + tx * 8 + j;
            if (gc < N) C[gr * N + gc] = acc[i][j];
        }
    }
}

// ---------------- RMSNorm + RoPE (kpe and q_pe in place) ----------------
__global__ void __launch_bounds__(256) prep_kernel(
    const float* __restrict__ latent, const float* __restrict__ lnw,
    const int* __restrict__ positions,
    float* __restrict__ kva, float* __restrict__ kpe, float* __restrict__ q)
{
    const int t = blockIdx.x;
    const int tid = threadIdx.x;
    __shared__ float red[8];
    const float* lat = latent + (size_t)t * HKVA;

    float s = 0.f;
#pragma unroll
    for (int i = tid; i < LKV; i += 256) { float v = lat[i]; s = fmaf(v, v, s); }
#pragma unroll
    for (int o = 16; o; o >>= 1) s += __shfl_xor_sync(~0u, s, o);
    if ((tid & 31) == 0) red[tid >> 5] = s;
    __syncthreads();
    if (tid == 0) {
        float tot = 0.f;
        for (int w = 0; w < 8; w++) tot += red[w];
        red[0] = tot;
    }
    __syncthreads();
    const float inv = rsqrtf(red[0] * (1.0f / LKV) + 1e-6f);

    for (int i = tid; i < LKV; i += 256)
        kva[(size_t)t * LKV + i] = lat[i] * inv * lnw[i];

    const float pos = (float)positions[t];

    // k_pe rope (32 pairs)
    if (tid < 32) {
        const int i = tid;
        const float inv_freq = 1.0f / powf(10000.0f, (i * 2.0f) / (float)DR);
        float sn, cs;
        sincosf(pos * inv_freq, &sn, &cs);
        const float x1 = lat[LKV + i];
        const float x2 = lat[LKV + 32 + i];
        kpe[(size_t)t * DR + i]      = x1 * cs - x2 * sn;
        kpe[(size_t)t * DR + 32 + i] = x2 * cs + x1 * sn;
    }

    // q_pe rope, all heads: H*32 = 512 pairs
    for (int idx = tid; idx < H * 32; idx += 256) {
        const int hh = idx >> 5;
        const int i  = idx & 31;
        const float inv_freq = 1.0f / powf(10000.0f, (i * 2.0f) / (float)DR);
        float sn, cs;
        sincosf(pos * inv_freq, &sn, &cs);
        float* qp = q + ((size_t)t * H + hh) * DQK + DN;
        const float x1 = qp[i];
        const float x2 = qp[32 + i];
        qp[i]      = x1 * cs - x2 * sn;
        qp[32 + i] = x2 * cs + x1 * sn;
    }
}

// ---------------- flash attention, fp32, causal ----------------
constexpr int BM = 64, BN = 64;
constexpr int KT_LD = 65;                       // pad: conflict-free transpose store
constexpr int PS_LD = 68;                       // pad: float4-aligned rows, cf stores
constexpr int QS_SZ = BM * DQK;                 // 12288
constexpr int KT_SZ = DQK * KT_LD;              // 12480
constexpr int VS_SZ = BN * DV;                  // 8192
constexpr int PS_SZ = BM * PS_LD;               // 4352
constexpr size_t ATT_SMEM_BYTES = (size_t)(QS_SZ + KT_SZ + VS_SZ + PS_SZ) * 4;

__global__ void __launch_bounds__(256, 1) attn_kernel(
    const float* __restrict__ q,    // [T][H][192], roped
    const float* __restrict__ kv,   // [T][H][256]
    const float* __restrict__ kpe,  // [T][64], roped
    float* __restrict__ out)        // [T][H*128]
{
    extern __shared__ float sm[];
    float* Qs = sm;
    float* Kt = Qs + QS_SZ;
    float* Vs = Kt + KT_SZ;
    float* Ps = Vs + VS_SZ;

    const int h  = blockIdx.y;
    const int qb = gridDim.x - 1 - blockIdx.x;    // big blocks first (balance)
    const int tid = threadIdx.x;
    const int warp = tid >> 5, lane = tid & 31;
    const int r0 = warp * 8;
    const int row_base = qb * BM;

    // load Q tile (coalesced; contiguous in smem)
    for (int idx = tid; idx < BM * DQK; idx += 256) {
        const int r = idx / DQK, c = idx - r * DQK;
        Qs[idx] = q[((size_t)(row_base + r) * H + h) * DQK + c];
    }

    float acc[8][4];
    float m_i[8], l_i[8];
#pragma unroll
    for (int r = 0; r < 8; r++) {
        m_i[r] = -1e30f; l_i[r] = 0.f;
        acc[r][0] = acc[r][1] = acc[r][2] = acc[r][3] = 0.f;
    }
    const float scale = 0.07216878364870322f;  // 1/sqrt(192)

    for (int jt = 0; jt <= qb; jt++) {
        const int s0 = jt * BN;
        __syncthreads();   // previous tile's PV reads of Vs done

        // K tile, stored transposed [k][c] (pad 65 -> conflict-free store+read)
        for (int idx = tid; idx < BN * DQK; idx += 256) {
            const int c = idx / DQK, k = idx - c * DQK;
            const float v = (k < DN)
                ? kv[((size_t)(s0 + c) * H + h) * 256 + k]
                : kpe[(size_t)(s0 + c) * DR + (k - DN)];
            Kt[k * KT_LD + c] = v;
        }
        // V tile [c][d]
        for (int idx = tid; idx < BN * DV; idx += 256) {
            const int c = idx >> 7, d = idx & 127;
            Vs[idx] = kv[((size_t)(s0 + c) * H + h) * 256 + DN + d];
        }
        __syncthreads();

        // ---- S = Q K^T : warp owns rows r0..r0+7; lane owns cols {lane, lane+32}
        float sv[8][2];
#pragma unroll
        for (int r = 0; r < 8; r++) { sv[r][0] = 0.f; sv[r][1] = 0.f; }

        for (int k = 0; k < DQK; k += 4) {
            const float ka0 = Kt[(k + 0) * KT_LD + lane];
            const float kb0 = Kt[(k + 0) * KT_LD + 32 + lane];
            const float ka1 = Kt[(k + 1) * KT_LD + lane];
            const float kb1 = Kt[(k + 1) * KT_LD + 32 + lane];
            const float ka2 = Kt[(k + 2) * KT_LD + lane];
            const float kb2 = Kt[(k + 2) * KT_LD + 32 + lane];
            const float ka3 = Kt[(k + 3) * KT_LD + lane];
            const float kb3 = Kt[(k + 3) * KT_LD + 32 + lane];
#pragma unroll
            for (int r = 0; r < 8; r++) {
                const float4 qv = *(const float4*)(Qs + (r0 + r) * DQK + k);
                sv[r][0] = fmaf(qv.x, ka0, fmaf(qv.y, ka1,
                           fmaf(qv.z, ka2, fmaf(qv.w, ka3, sv[r][0]))));
                sv[r][1] = fmaf(qv.x, kb0, fmaf(qv.y, kb1,
                           fmaf(qv.z, kb2, fmaf(qv.w, kb3, sv[r][1]))));
            }
        }

        // ---- scale, causal mask, online softmax
        const bool diag = (jt == qb);
#pragma unroll
        for (int r = 0; r < 8; r++) {
            const int row_local = r0 + r;
            float s0v = sv[r][0] * scale;
            float s1v = sv[r][1] * scale;
            if (diag) {
                if (lane      > row_local) s0v = -3.0e38f;
                if (lane + 32 > row_local) s1v = -3.0e38f;
            }
            float mx = fmaxf(s0v, s1v);
#pragma unroll
            for (int o = 16; o; o >>= 1) mx = fmaxf(mx, __shfl_xor_sync(~0u, mx, o));
            const float mnew = fmaxf(m_i[r], mx);
            const float p0 = __expf(s0v - mnew);
            const float p1 = __expf(s1v - mnew);
            const float corr = __expf(m_i[r] - mnew);
            float rs = p0 + p1;
#pragma unroll
            for (int o = 16; o; o >>= 1) rs += __shfl_xor_sync(~0u, rs, o);
            l_i[r] = l_i[r] * corr + rs;
            m_i[r] = mnew;
            acc[r][0] *= corr; acc[r][1] *= corr;
            acc[r][2] *= corr; acc[r][3] *= corr;
            Ps[(r0 + r) * PS_LD + lane]      = p0;
            Ps[(r0 + r) * PS_LD + 32 + lane] = p1;
        }
        __syncwarp();   // Ps rows are warp-private; order writes before reads

        // ---- O += P V : lane owns cols d = lane*4 .. lane*4+3
        for (int c = 0; c < BN; c += 4) {
            const float4 v0 = *(const float4*)(Vs + (c + 0) * DV + (lane << 2));
            const float4 v1 = *(const float4*)(Vs + (c + 1) * DV + (lane << 2));
            const float4 v2 = *(const float4*)(Vs + (c + 2) * DV + (lane << 2));
            const float4 v3 = *(const float4*)(Vs + (c + 3) * DV + (lane << 2));
#pragma unroll
            for (int r = 0; r < 8; r++) {
                const float4 p = *(const float4*)(Ps + (r0 + r) * PS_LD + c);
                acc[r][0] = fmaf(p.x, v0.x, fmaf(p.y, v1.x,
                            fmaf(p.z, v2.x, fmaf(p.w, v3.x, acc[r][0]))));
                acc[r][1] = fmaf(p.x, v0.y, fmaf(p.y, v1.y,
                            fmaf(p.z, v2.y, fmaf(p.w, v3.y, acc[r][1]))));
                acc[r][2] = fmaf(p.x, v0.z, fmaf(p.y, v1.z,
                            fmaf(p.z, v2.z, fmaf(p.w, v3.z, acc[r][2]))));
                acc[r][3] = fmaf(p.x, v0.w, fmaf(p.y, v1.w,
                            fmaf(p.z, v2.w, fmaf(p.w, v3.w, acc[r][3]))));
            }
        }
    }

    // ---- epilogue
#pragma unroll
    for (int r = 0; r < 8; r++) {
        const float inv = 1.0f / l_i[r];
        const size_t row = (size_t)(row_base + r0 + r);
        float4 o;
        o.x = acc[r][0] * inv; o.y = acc[r][1] * inv;
        o.z = acc[r][2] * inv; o.w = acc[r][3] * inv;
        *(float4*)(out + row * (H * DV) + h * DV + (lane << 2)) = o;
    }
}

// ---------------- host ----------------
static inline void launch_sgemm(const float* A, const float* B, float* C,
                                int M, int N, int K)
{
    dim3 grid((N + 127) / 128, (M + 127) / 128);
    sgemm_kernel<<<grid, 256>>>(A, B, C, M, N, K);
}

extern "C" void kernel_launch(void* const* d_in, const int* in_sizes, int n_in,
                              void* d_out, int out_size)
{
    const int*   positions = (const int*)d_in[0];
    const float* hidden    = (const float*)d_in[1];
    const float* Wq        = (const float*)d_in[2];
    const float* Wkva      = (const float*)d_in[3];
    const float* lnw       = (const float*)d_in[4];
    const float* Wkvb      = (const float*)d_in[5];
    const float* Wo        = (const float*)d_in[6];
    float* out = (float*)d_out;

    float *p_q, *p_latent, *p_kva, *p_kpe, *p_kv, *p_attn;
    cudaGetSymbolAddress((void**)&p_q,      g_q);
    cudaGetSymbolAddress((void**)&p_latent, g_latent);
    cudaGetSymbolAddress((void**)&p_kva,    g_kva);
    cudaGetSymbolAddress((void**)&p_kpe,    g_kpe);
    cudaGetSymbolAddress((void**)&p_kv,     g_kv);
    cudaGetSymbolAddress((void**)&p_attn,   g_attn);

    cudaFuncSetAttribute(attn_kernel, cudaFuncAttributeMaxDynamicSharedMemorySize,
                         (int)ATT_SMEM_BYTES);

    // 1. q = hidden @ Wq              [4096, 3072]
    launch_sgemm(hidden, Wq, p_q, T, H * DQK, HID);
    // 2. latent = hidden @ Wkva       [4096, 576]
    launch_sgemm(hidden, Wkva, p_latent, T, HKVA, HID);
    // 3. rmsnorm + rope (kpe, q_pe in place)
    prep_kernel<<<T, 256>>>(p_latent, lnw, positions, p_kva, p_kpe, p_q);
    // 4. kv = kva @ Wkvb              [4096, 4096]
    launch_sgemm(p_kva, Wkvb, p_kv, T, H * (DN + DV), LKV);
    // 5. attention -> [4096, 2048]
    {
        dim3 grid(T / BM, H);
        attn_kernel<<<grid, 256, ATT_SMEM_BYTES>>>(p_q, p_kv, p_kpe, p_attn);
    }
    // 6. out = attn @ Wo              [4096, 2048]
    launch_sgemm(p_attn, Wo, out, T, HID, H * DV);
}

// round 7
// speedup vs baseline: 1.6809x; 1.6809x over previous
#include <cuda_runtime.h>
#include <math.h>

// ---------------- problem constants ----------------
constexpr int T    = 4096;
constexpr int HID  = 2048;
constexpr int H    = 16;
constexpr int DN   = 128;   // D_NOPE
constexpr int DR   = 64;    // D_ROPE
constexpr int DQK  = 192;   // DN + DR
constexpr int DV   = 128;
constexpr int LKV  = 512;
constexpr int HKVA = LKV + DR;  // 576

// ---------------- device scratch ----------------
__device__ float g_q[(size_t)T * H * DQK];
__device__ float g_latent[(size_t)T * HKVA];
__device__ float g_kva[(size_t)T * LKV];
__device__ float g_kpe[(size_t)T * DR];
__device__ float g_kv[(size_t)T * H * (DN + DV)];
__device__ float g_attn[(size_t)T * H * DV];

// ---------------- tf32 helpers ----------------
__device__ __forceinline__ unsigned f2tf(float x) {
    unsigned r; asm("cvt.rna.tf32.f32 %0, %1;" : "=r"(r) : "f"(x)); return r;
}
__device__ __forceinline__ void mma_tf32_16n8k8(float* d,
    unsigned a0, unsigned a1, unsigned a2, unsigned a3,
    unsigned b0, unsigned b1)
{
    asm("mma.sync.aligned.m16n8k8.row.col.f32.tf32.tf32.f32 "
        "{%0,%1,%2,%3},{%4,%5,%6,%7},{%8,%9},{%0,%1,%2,%3};"
        : "+f"(d[0]), "+f"(d[1]), "+f"(d[2]), "+f"(d[3])
        : "r"(a0), "r"(a1), "r"(a2), "r"(a3), "r"(b0), "r"(b1));
}

// ================= TF32 GEMM: C[M,N] = A[M,K] @ B[K,N] =================
// 256 threads, BM=BN=128, BK=16. Warp grid 2(m)x4(n): warp tile 64x32.
constexpr int GBK = 16;

__global__ void __launch_bounds__(256) mla_gemm(
    const float* __restrict__ A, const float* __restrict__ B,
    float* __restrict__ C, int M, int N, int K, int round_out)
{
    __shared__ unsigned As[128][GBK + 4];   // [m][k], pad 4
    __shared__ unsigned Bs[GBK][128 + 4];   // [k][n], pad 4

    const int tid = threadIdx.x, lane = tid & 31, warp = tid >> 5;
    const int bm = blockIdx.y * 128, bn = blockIdx.x * 128;
    const int wm = (warp & 1) * 64, wn = (warp >> 1) * 32;
    const int rA = lane >> 2, cA = lane & 3;

    const int a_row = tid >> 1, a_kc = (tid & 1) * 8;
    const int b_c4  = (tid & 31) * 4, b_r = warp;   // rows b_r, b_r+8

    float acc[4][4][4];
#pragma unroll
    for (int mt = 0; mt < 4; mt++)
#pragma unroll
        for (int nt = 0; nt < 4; nt++) {
            acc[mt][nt][0] = 0.f; acc[mt][nt][1] = 0.f;
            acc[mt][nt][2] = 0.f; acc[mt][nt][3] = 0.f;
        }

    const float* Ap = A + (size_t)(bm + a_row) * K + a_kc;
    const int gcn = bn + b_c4;
    const bool b_ok = gcn < N;              // N % 4 == 0 always here

    float4 ra0, ra1, rb0, rb1;
    ra0 = *(const float4*)(Ap);
    ra1 = *(const float4*)(Ap + 4);
    if (b_ok) {
        rb0 = *(const float4*)(B + (size_t)(b_r)     * N + gcn);
        rb1 = *(const float4*)(B + (size_t)(b_r + 8) * N + gcn);
    } else { rb0 = make_float4(0.f,0.f,0.f,0.f); rb1 = rb0; }

    for (int k0 = 0; k0 < K; k0 += GBK) {
        As[a_row][a_kc + 0] = f2tf(ra0.x); As[a_row][a_kc + 1] = f2tf(ra0.y);
        As[a_row][a_kc + 2] = f2tf(ra0.z); As[a_row][a_kc + 3] = f2tf(ra0.w);
        As[a_row][a_kc + 4] = f2tf(ra1.x); As[a_row][a_kc + 5] = f2tf(ra1.y);
        As[a_row][a_kc + 6] = f2tf(ra1.z); As[a_row][a_kc + 7] = f2tf(ra1.w);
        Bs[b_r][b_c4 + 0] = f2tf(rb0.x); Bs[b_r][b_c4 + 1] = f2tf(rb0.y);
        Bs[b_r][b_c4 + 2] = f2tf(rb0.z); Bs[b_r][b_c4 + 3] = f2tf(rb0.w);
        Bs[b_r + 8][b_c4 + 0] = f2tf(rb1.x); Bs[b_r + 8][b_c4 + 1] = f2tf(rb1.y);
        Bs[b_r + 8][b_c4 + 2] = f2tf(rb1.z); Bs[b_r + 8][b_c4 + 3] = f2tf(rb1.w);
        __syncthreads();

        if (k0 + GBK < K) {
            ra0 = *(const float4*)(Ap + k0 + GBK);
            ra1 = *(const float4*)(Ap + k0 + GBK + 4);
            if (b_ok) {
                rb0 = *(const float4*)(B + (size_t)(k0 + GBK + b_r)     * N + gcn);
                rb1 = *(const float4*)(B + (size_t)(k0 + GBK + b_r + 8) * N + gcn);
            }
        }

#pragma unroll
        for (int ks = 0; ks < GBK; ks += 8) {
            unsigned af[4][4];
#pragma unroll
            for (int mt = 0; mt < 4; mt++) {
                const int r = wm + mt * 16 + rA;
                const int c = ks + cA;
                af[mt][0] = As[r][c];     af[mt][1] = As[r + 8][c];
                af[mt][2] = As[r][c + 4]; af[mt][3] = As[r + 8][c + 4];
            }
#pragma unroll
            for (int nt = 0; nt < 4; nt++) {
                const unsigned b0 = Bs[ks + cA][wn + nt * 8 + rA];
                const unsigned b1 = Bs[ks + cA + 4][wn + nt * 8 + rA];
#pragma unroll
                for (int mt = 0; mt < 4; mt++)
                    mma_tf32_16n8k8(acc[mt][nt],
                        af[mt][0], af[mt][1], af[mt][2], af[mt][3], b0, b1);
            }
        }
        __syncthreads();
    }

#pragma unroll
    for (int mt = 0; mt < 4; mt++) {
        const int r0 = bm + wm + mt * 16 + rA;
#pragma unroll
        for (int nt = 0; nt < 4; nt++) {
            const int c0 = bn + wn + nt * 8 + cA * 2;
            if (c0 < N) {
                float2 v0, v1;
                v0.x = acc[mt][nt][0]; v0.y = acc[mt][nt][1];
                v1.x = acc[mt][nt][2]; v1.y = acc[mt][nt][3];
                if (round_out) {
                    v0.x = __uint_as_float(f2tf(v0.x));
                    v0.y = __uint_as_float(f2tf(v0.y));
                    v1.x = __uint_as_float(f2tf(v1.x));
                    v1.y = __uint_as_float(f2tf(v1.y));
                }
                *(float2*)(C + (size_t)r0 * N + c0)       = v0;
                *(float2*)(C + (size_t)(r0 + 8) * N + c0) = v1;
            }
        }
    }
}

// ================= RMSNorm + RoPE + tf32 rounding =================
__global__ void __launch_bounds__(256) mla_prep(
    const float* __restrict__ latent, const float* __restrict__ lnw,
    const int* __restrict__ positions,
    float* __restrict__ kva, float* __restrict__ kpe, float* __restrict__ q)
{
    const int t = blockIdx.x;
    const int tid = threadIdx.x;
    __shared__ float red[8];
    const float* lat = latent + (size_t)t * HKVA;

    float s = 0.f;
    for (int i = tid; i < LKV; i += 256) { float v = lat[i]; s = fmaf(v, v, s); }
#pragma unroll
    for (int o = 16; o; o >>= 1) s += __shfl_xor_sync(~0u, s, o);
    if ((tid & 31) == 0) red[tid >> 5] = s;
    __syncthreads();
    if (tid == 0) {
        float tot = 0.f;
        for (int w = 0; w < 8; w++) tot += red[w];
        red[0] = tot;
    }
    __syncthreads();
    const float inv = rsqrtf(red[0] * (1.0f / LKV) + 1e-6f);

    for (int i = tid; i < LKV; i += 256)
        kva[(size_t)t * LKV + i] = lat[i] * inv * lnw[i];

    const float pos = (float)positions[t];

    if (tid < 32) {
        const int i = tid;
        const float inv_freq = 1.0f / powf(10000.0f, (i * 2.0f) / (float)DR);
        float sn, cs; sincosf(pos * inv_freq, &sn, &cs);
        const float x1 = lat[LKV + i];
        const float x2 = lat[LKV + 32 + i];
        kpe[(size_t)t * DR + i]      = __uint_as_float(f2tf(x1 * cs - x2 * sn));
        kpe[(size_t)t * DR + 32 + i] = __uint_as_float(f2tf(x2 * cs + x1 * sn));
    }

    for (int idx = tid; idx < H * 32; idx += 256) {
        const int hh = idx >> 5, i = idx & 31;
        const float inv_freq = 1.0f / powf(10000.0f, (i * 2.0f) / (float)DR);
        float sn, cs; sincosf(pos * inv_freq, &sn, &cs);
        float* qp = q + ((size_t)t * H + hh) * DQK + DN;
        const float x1 = qp[i];
        const float x2 = qp[32 + i];
        qp[i]      = x1 * cs - x2 * sn;
        qp[32 + i] = x2 * cs + x1 * sn;
    }
    __syncthreads();

    for (int idx = tid; idx < H * DQK; idx += 256) {
        const size_t o = (size_t)t * H * DQK + idx;
        q[o] = __uint_as_float(f2tf(q[o]));
    }
}

// ================= Flash attention, tf32 mma, causal =================
constexpr int ABM = 64, ABN = 64;
constexpr int KT_LD = 68;
constexpr int VS_LD = 132;
constexpr size_t ATT_SMEM = (size_t)(DQK * KT_LD + ABN * VS_LD) * 4;  // 86016 B

__global__ void __launch_bounds__(128) mla_attn(
    const float* __restrict__ q,    // [T][H][192], tf32-rounded
    const float* __restrict__ kv,   // [T][H][256], tf32-rounded
    const float* __restrict__ kpe,  // [T][64],     tf32-rounded
    float* __restrict__ out)        // [T][H*128]
{
    extern __shared__ float sm[];
    float* Kt = sm;                  // [192][68]
    float* Vs = sm + DQK * KT_LD;    // [64][132]

    const int h   = blockIdx.y;
    const int qb  = gridDim.x - 1 - blockIdx.x;
    const int tid = threadIdx.x, warp = tid >> 5, lane = tid & 31;
    const int rA = lane >> 2, cA = lane & 3;
    const int row0 = qb * ABM + warp * 16;
    const float scale = 0.07216878364870322f;   // 1/sqrt(192)
    const size_t qstride = (size_t)H * DQK;
    const float* qbase = q + ((size_t)row0 * H + h) * DQK;

    float acc[16][4];
#pragma unroll
    for (int nt = 0; nt < 16; nt++) {
        acc[nt][0] = 0.f; acc[nt][1] = 0.f; acc[nt][2] = 0.f; acc[nt][3] = 0.f;
    }
    float m0 = -1e30f, m1 = -1e30f, l0 = 0.f, l1 = 0.f;

    const int srcA = (lane & ~3) | (cA >> 1);
    const int srcB = srcA + 2;
    const bool odd = (cA & 1) != 0;

    for (int jt = 0; jt <= qb; jt++) {
        const int s0 = jt * ABN;
        __syncthreads();
        for (int idx = tid; idx < ABN * DQK; idx += 128) {
            const int c = idx / DQK, k = idx - c * DQK;
            const float v = (k < DN)
                ? kv[((size_t)(s0 + c) * H + h) * 256 + k]
                : kpe[(size_t)(s0 + c) * DR + (k - DN)];
            Kt[k * KT_LD + c] = v;
        }
        for (int i = tid; i < ABN * DV / 4; i += 128) {
            const int c = i >> 5, d4 = (i & 31) * 4;
            *(float4*)(Vs + c * VS_LD + d4) =
                *(const float4*)(kv + ((size_t)(s0 + c) * H + h) * 256 + DN + d4);
        }
        __syncthreads();

        // ---- S = Q K^T ----
        float sfr[8][4];
#pragma unroll
        for (int nt = 0; nt < 8; nt++) {
            sfr[nt][0] = 0.f; sfr[nt][1] = 0.f; sfr[nt][2] = 0.f; sfr[nt][3] = 0.f;
        }

        for (int kk = 0; kk < DQK / 8; kk++) {
            const float* qp = qbase + kk * 8 + cA;
            const unsigned a0 = __float_as_uint(qp[(size_t)rA * qstride]);
            const unsigned a1 = __float_as_uint(qp[(size_t)(rA + 8) * qstride]);
            const unsigned a2 = __float_as_uint(qp[(size_t)rA * qstride + 4]);
            const unsigned a3 = __float_as_uint(qp[(size_t)(rA + 8) * qstride + 4]);
            const float* kt0 = Kt + (kk * 8 + cA) * KT_LD + rA;
            const float* kt1 = kt0 + 4 * KT_LD;
#pragma unroll
            for (int nt = 0; nt < 8; nt++) {
                const unsigned b0 = __float_as_uint(kt0[nt * 8]);
                const unsigned b1 = __float_as_uint(kt1[nt * 8]);
                mma_tf32_16n8k8(sfr[nt], a0, a1, a2, a3, b0, b1);
            }
        }

        // ---- scale + causal mask ----
        const bool diag = (jt == qb);
        const int gr0 = row0 + rA, gr1 = gr0 + 8;
#pragma unroll
        for (int nt = 0; nt < 8; nt++) {
            const int gc = s0 + nt * 8 + cA * 2;
            sfr[nt][0] *= scale; sfr[nt][1] *= scale;
            sfr[nt][2] *= scale; sfr[nt][3] *= scale;
            if (diag) {
                if (gc     > gr0) sfr[nt][0] = -1e30f;
                if (gc + 1 > gr0) sfr[nt][1] = -1e30f;
                if (gc     > gr1) sfr[nt][2] = -1e30f;
                if (gc + 1 > gr1) sfr[nt][3] = -1e30f;
            }
        }

        // ---- online softmax (quad-level row reductions) ----
        float mx0 = -1e30f, mx1 = -1e30f;
#pragma unroll
        for (int nt = 0; nt < 8; nt++) {
            mx0 = fmaxf(mx0, fmaxf(sfr[nt][0], sfr[nt][1]));
            mx1 = fmaxf(mx1, fmaxf(sfr[nt][2], sfr[nt][3]));
        }
        mx0 = fmaxf(mx0, __shfl_xor_sync(~0u, mx0, 1));
        mx0 = fmaxf(mx0, __shfl_xor_sync(~0u, mx0, 2));
        mx1 = fmaxf(mx1, __shfl_xor_sync(~0u, mx1, 1));
        mx1 = fmaxf(mx1, __shfl_xor_sync(~0u, mx1, 2));
        const float nm0 = fmaxf(m0, mx0), nm1 = fmaxf(m1, mx1);
        const float corr0 = __expf(m0 - nm0), corr1 = __expf(m1 - nm1);
        m0 = nm0; m1 = nm1;

        float rs0 = 0.f, rs1 = 0.f;
#pragma unroll
        for (int nt = 0; nt < 8; nt++) {
            sfr[nt][0] = __expf(sfr[nt][0] - nm0);
            sfr[nt][1] = __expf(sfr[nt][1] - nm0);
            sfr[nt][2] = __expf(sfr[nt][2] - nm1);
            sfr[nt][3] = __expf(sfr[nt][3] - nm1);
            rs0 += sfr[nt][0] + sfr[nt][1];
            rs1 += sfr[nt][2] + sfr[nt][3];
        }
        rs0 += __shfl_xor_sync(~0u, rs0, 1); rs0 += __shfl_xor_sync(~0u, rs0, 2);
        rs1 += __shfl_xor_sync(~0u, rs1, 1); rs1 += __shfl_xor_sync(~0u, rs1, 2);
        l0 = l0 * corr0 + rs0;
        l1 = l1 * corr1 + rs1;
#pragma unroll
        for (int nt = 0; nt < 16; nt++) {
            acc[nt][0] *= corr0; acc[nt][1] *= corr0;
            acc[nt][2] *= corr1; acc[nt][3] *= corr1;
        }

        // ---- O += P V (P fragment -> A fragment via quad shuffles) ----
#pragma unroll
        for (int kk = 0; kk < 8; kk++) {
            const float p0 = sfr[kk][0], p1 = sfr[kk][1];
            const float p2 = sfr[kk][2], p3 = sfr[kk][3];
            const float vA0 = __shfl_sync(~0u, p0, srcA);
            const float vA1 = __shfl_sync(~0u, p1, srcA);
            const float vB0 = __shfl_sync(~0u, p0, srcB);
            const float vB1 = __shfl_sync(~0u, p1, srcB);
            const float wA0 = __shfl_sync(~0u, p2, srcA);
            const float wA1 = __shfl_sync(~0u, p3, srcA);
            const float wB0 = __shfl_sync(~0u, p2, srcB);
            const float wB1 = __shfl_sync(~0u, p3, srcB);
            const unsigned a0 = f2tf(odd ? vA1 : vA0);
            const unsigned a1 = f2tf(odd ? wA1 : wA0);
            const unsigned a2 = f2tf(odd ? vB1 : vB0);
            const unsigned a3 = f2tf(odd ? wB1 : wB0);
            const float* vs0 = Vs + (kk * 8 + cA) * VS_LD + rA;
            const float* vs1 = vs0 + 4 * VS_LD;
#pragma unroll
            for (int np = 0; np < 8; np++) {
                const unsigned b00 = __float_as_uint(vs0[(2 * np) * 8]);
                const unsigned b01 = __float_as_uint(vs1[(2 * np) * 8]);
                const unsigned b10 = __float_as_uint(vs0[(2 * np + 1) * 8]);
                const unsigned b11 = __float_as_uint(vs1[(2 * np + 1) * 8]);
                mma_tf32_16n8k8(acc[2 * np],     a0, a1, a2, a3, b00, b01);
                mma_tf32_16n8k8(acc[2 * np + 1], a0, a1, a2, a3, b10, b11);
            }
        }
    }

    // ---- epilogue ----
    const float inv0 = 1.f / l0, inv1 = 1.f / l1;
#pragma unroll
    for (int nt = 0; nt < 16; nt++) {
        const int col = h * DV + nt * 8 + cA * 2;
        float2 v0, v1;
        v0.x = acc[nt][0] * inv0; v0.y = acc[nt][1] * inv0;
        v1.x = acc[nt][2] * inv1; v1.y = acc[nt][3] * inv1;
        *(float2*)(out + (size_t)(row0 + rA) * (H * DV) + col)     = v0;
        *(float2*)(out + (size_t)(row0 + rA + 8) * (H * DV) + col) = v1;
    }
}

// ---------------- host ----------------
static inline void launch_gemm(const float* A, const float* B, float* C,
                               int M, int N, int K, int round_out)
{
    dim3 grid((N + 127) / 128, M / 128);
    mla_gemm<<<grid, 256>>>(A, B, C, M, N, K, round_out);
}

extern "C" void kernel_launch(void* const* d_in, const int* in_sizes, int n_in,
                              void* d_out, int out_size)
{
    const int*   positions = (const int*)d_in[0];
    const float* hidden    = (const float*)d_in[1];
    const float* Wq        = (const float*)d_in[2];
    const float* Wkva      = (const float*)d_in[3];
    const float* lnw       = (const float*)d_in[4];
    const float* Wkvb      = (const float*)d_in[5];
    const float* Wo        = (const float*)d_in[6];
    float* out = (float*)d_out;

    float *p_q, *p_latent, *p_kva, *p_kpe, *p_kv, *p_attn;
    cudaGetSymbolAddress((void**)&p_q,      g_q);
    cudaGetSymbolAddress((void**)&p_latent, g_latent);
    cudaGetSymbolAddress((void**)&p_kva,    g_kva);
    cudaGetSymbolAddress((void**)&p_kpe,    g_kpe);
    cudaGetSymbolAddress((void**)&p_kv,     g_kv);
    cudaGetSymbolAddress((void**)&p_attn,   g_attn);

    cudaFuncSetAttribute(mla_attn, cudaFuncAttributeMaxDynamicSharedMemorySize,
                         (int)ATT_SMEM);

    // 1. q = hidden @ Wq                      [4096, 3072]
    launch_gemm(hidden, Wq, p_q, T, H * DQK, HID, 0);
    // 2. latent = hidden @ Wkva               [4096, 576]
    launch_gemm(hidden, Wkva, p_latent, T, HKVA, HID, 0);
    // 3. rmsnorm + rope + tf32-round q/kpe
    mla_prep<<<T, 256>>>(p_latent, lnw, positions, p_kva, p_kpe, p_q);
    // 4. kv = kva @ Wkvb (tf32-rounded output) [4096, 4096]
    launch_gemm(p_kva, Wkvb, p_kv, T, H * (DN + DV), LKV, 1);
    // 5. attention
    {
        dim3 grid(T / ABM, H);
        mla_attn<<<grid, 128, ATT_SMEM>>>(p_q, p_kv, p_kpe, p_attn);
    }
    // 6. out = attn @ Wo                      [4096, 2048]
    launch_gemm(p_attn, Wo, out, T, HID, H * DV, 0);
}